// round 4
// baseline (speedup 1.0000x reference)
#include <cuda_runtime.h>
#include <cuda_bf16.h>

#define IMG_S 4096
#define NDOTS 100
#define TILE_W 64
#define SUB_H 16
#define NSUB 4            // block region = 64 x 64
#define NTHREADS 256

__global__ __launch_bounds__(NTHREADS)
void patch_dots_kernel(const float* __restrict__ patch,
                       const float* __restrict__ centers,
                       const float* __restrict__ radii,
                       const float* __restrict__ colors,
                       float* __restrict__ out)
{
    __shared__ float sxc[NDOTS];
    __shared__ float syc[NDOTS];
    __shared__ float sr2[NDOTS];
    __shared__ float scr[NDOTS];
    __shared__ float scg[NDOTS];
    __shared__ float scb[NDOTS];
    __shared__ unsigned s_isect[NSUB][4];
    __shared__ unsigned s_full[NSUB][4];

    const int tid = threadIdx.x;

    const int blocks_x = IMG_S / TILE_W;            // 64
    const int tx0 = (blockIdx.x & (blocks_x - 1)) * TILE_W;
    const int ty0 = (blockIdx.x / blocks_x) * (SUB_H * NSUB);

    // ---- Load dot parameters once per block (exact reference fp32 math) ----
    if (tid < NDOTS) {
        float cx = floorf(centers[2 * tid + 0] * (float)IMG_S);
        float cy = floorf(centers[2 * tid + 1] * (float)IMG_S);
        float r  = floorf(radii[tid] * ((float)IMG_S / 5.0f));
        sxc[tid] = cx;
        syc[tid] = cy;
        sr2[tid] = r * r;
        scr[tid] = colors[3 * tid + 0];
        scg[tid] = colors[3 * tid + 1];
        scb[tid] = colors[3 * tid + 2];
    }
    __syncthreads();

    // ---- Cull all 4 sub-tiles in one pass ----
    if (tid < 128) {
        const float x0 = (float)tx0, x1 = (float)(tx0 + TILE_W - 1);
        float cx = 0.f, cy = 0.f, r2 = -1.f;
        float nxx = 0.f, fxx = 0.f;
        if (tid < NDOTS) {
            cx = sxc[tid]; cy = syc[tid]; r2 = sr2[tid];
            float nx = fminf(fmaxf(cx, x0), x1) - cx;     // nearest-x dist
            nxx = nx * nx;
            float fxd = fmaxf(fabsf(x0 - cx), fabsf(x1 - cx)); // farthest-x dist
            fxx = fxd * fxd;
        }
        #pragma unroll
        for (int k = 0; k < NSUB; ++k) {
            bool isect = false, full = false;
            if (tid < NDOTS) {
                float y0 = (float)(ty0 + k * SUB_H);
                float y1 = y0 + (float)(SUB_H - 1);
                float ny = fminf(fmaxf(cy, y0), y1) - cy;
                isect = fmaf(ny, ny, nxx) <= r2;
                float fyd = fmaxf(fabsf(y0 - cy), fabsf(y1 - cy));
                full = fmaf(fyd, fyd, fxx) <= r2;
            }
            unsigned mi = __ballot_sync(0xFFFFFFFFu, isect);
            unsigned mf = __ballot_sync(0xFFFFFFFFu, full);
            if ((tid & 31) == 0) {
                s_isect[k][tid >> 5] = mi;
                s_full[k][tid >> 5]  = mf;
            }
        }
    }
    __syncthreads();

    // ---- Per-thread quad geometry (constant across sub-tiles) ----
    const int lx = (tid & 15) * 4;        // 0..60
    const int ly = tid >> 4;              // 0..15
    const int x  = tx0 + lx;
    const float fx = (float)x;

    const unsigned plane_q = (IMG_S / 4) * IMG_S;
    const unsigned row_q   = IMG_S / 4;
    const float4* __restrict__ p4 = (const float4*)patch;
    float4* __restrict__ o4 = (float4*)out;

    #pragma unroll 1
    for (int k = 0; k < NSUB; ++k) {
        unsigned m0 = s_isect[k][0], m1 = s_isect[k][1];
        unsigned m2 = s_isect[k][2], m3 = s_isect[k][3];
        const unsigned f0 = s_full[k][0], f1 = s_full[k][1];
        const unsigned f2 = s_full[k][2], f3 = s_full[k][3];

        int jmax = -1;
        if (f3)      jmax = 96 + (31 - __clz(f3));
        else if (f2) jmax = 64 + (31 - __clz(f2));
        else if (f1) jmax = 32 + (31 - __clz(f1));
        else if (f0) jmax =      (31 - __clz(f0));

        const bool tile_full = (jmax >= 0);
        if (tile_full) {
            if (jmax >= 96)      { m0 = m1 = m2 = 0; m3 &= 0xFFFFFFFFu << (jmax - 96); }
            else if (jmax >= 64) { m0 = m1 = 0;      m2 &= 0xFFFFFFFFu << (jmax - 64); }
            else if (jmax >= 32) { m0 = 0;           m1 &= 0xFFFFFFFFu << (jmax - 32); }
            else                 {                   m0 &= 0xFFFFFFFFu <<  jmax;       }
        }

        const int y = ty0 + k * SUB_H + ly;
        const unsigned qidx = (unsigned)y * row_q + (unsigned)(x >> 2);

        const int survivors = __popc(m0) + __popc(m1) + __popc(m2) + __popc(m3);

        int i0 = -1, i1 = -1, i2 = -1, i3 = -1;

        if (tile_full && survivors == 1) {
            // Uniform sub-tile: single covering dot, nothing above it.
            i0 = i1 = i2 = i3 = jmax;
        } else {
            const float fy = (float)y;

            // Prefetch patch quad early only when misses are possible.
            float4 pr, pg, pb;
            if (!tile_full) {
                pr = p4[qidx];
                pg = p4[qidx + plane_q];
                pb = p4[qidx + 2 * plane_q];
            }

            int hitmask = 0;
            unsigned mm;
            #define TEST_LANE(J, DXJ)                                          \
                if (!(hitmask & (1 << J))) {                                   \
                    float dx = (DXJ);                                          \
                    if (fmaf(dx, dx, dy2) <= r2) {                             \
                        hitmask |= (1 << J);                                   \
                        i##J = i;                                              \
                    }                                                          \
                }

            #define SCAN_WORD(MW, BASE)                                        \
                mm = (MW);                                                     \
                while (mm) {                                                   \
                    int b = 31 - __clz(mm);                                    \
                    int i = (BASE) + b;                                        \
                    float dy = fy - syc[i];                                    \
                    float dy2 = dy * dy;                                       \
                    float r2  = sr2[i];                                        \
                    float dx0 = fx - sxc[i];                                   \
                    TEST_LANE(0, dx0)                                          \
                    TEST_LANE(1, dx0 + 1.0f)                                   \
                    TEST_LANE(2, dx0 + 2.0f)                                   \
                    TEST_LANE(3, dx0 + 3.0f)                                   \
                    if (hitmask == 0xF) break;                                 \
                    mm &= ~(1u << b);                                          \
                }

            SCAN_WORD(m3, 96)
            if (hitmask != 0xF) { SCAN_WORD(m2, 64) }
            if (hitmask != 0xF) { SCAN_WORD(m1, 32) }
            if (hitmask != 0xF) { SCAN_WORD(m0, 0)  }
            #undef SCAN_WORD
            #undef TEST_LANE

            if (hitmask != 0xF) {
                // misses only possible when !tile_full (patch prefetched)
                float4 vr, vg, vb;
                vr.x = (i0 >= 0) ? scr[i0] : pr.x;
                vr.y = (i1 >= 0) ? scr[i1] : pr.y;
                vr.z = (i2 >= 0) ? scr[i2] : pr.z;
                vr.w = (i3 >= 0) ? scr[i3] : pr.w;
                vg.x = (i0 >= 0) ? scg[i0] : pg.x;
                vg.y = (i1 >= 0) ? scg[i1] : pg.y;
                vg.z = (i2 >= 0) ? scg[i2] : pg.z;
                vg.w = (i3 >= 0) ? scg[i3] : pg.w;
                vb.x = (i0 >= 0) ? scb[i0] : pb.x;
                vb.y = (i1 >= 0) ? scb[i1] : pb.y;
                vb.z = (i2 >= 0) ? scb[i2] : pb.z;
                vb.w = (i3 >= 0) ? scb[i3] : pb.w;
                o4[qidx]               = vr;
                o4[qidx + plane_q]     = vg;
                o4[qidx + 2 * plane_q] = vb;
                continue;
            }
        }

        // All four lanes hit: pure color stores via shared lookup.
        o4[qidx]               = make_float4(scr[i0], scr[i1], scr[i2], scr[i3]);
        o4[qidx + plane_q]     = make_float4(scg[i0], scg[i1], scg[i2], scg[i3]);
        o4[qidx + 2 * plane_q] = make_float4(scb[i0], scb[i1], scb[i2], scb[i3]);
    }
}

extern "C" void kernel_launch(void* const* d_in, const int* in_sizes, int n_in,
                              void* d_out, int out_size)
{
    const float* patch   = (const float*)d_in[0];
    const float* centers = (const float*)d_in[1];
    const float* radii   = (const float*)d_in[2];
    const float* colors  = (const float*)d_in[3];
    float* out = (float*)d_out;

    const int blocks = (IMG_S / TILE_W) * (IMG_S / (SUB_H * NSUB));  // 64 * 64 = 4096
    patch_dots_kernel<<<blocks, NTHREADS>>>(patch, centers, radii, colors, out);
}